// round 3
// baseline (speedup 1.0000x reference)
#include <cuda_runtime.h>
#include <cstdint>

#define NN 256
#define DD 768
#define EE 768
#define FF 96
#define HH 8
#define LL 2
#define ALPHAV 0.2f
#define NEGV (-9000000000000000.0f)

// ---------------- device scratch (no allocations allowed) ----------------
__device__ float g_wk_a2[LL*HH*EE];               // 48 KB : Wk_e @ a2 per (l,h)
__device__ float g_se[(size_t)LL*HH*NN*NN];       // 4 MB  : edge score contribution, both layers
__device__ float g_hq[HH*NN*FF];                  // per-layer projections
__device__ float g_hk[HH*NN*FF];
__device__ float g_hv[HH*NN*FF];
__device__ float g_sq[HH*NN];
__device__ float g_sk[HH*NN];
__device__ float g_att[HH*NN*NN];                 // 2 MB
__device__ float g_ec[HH*NN*EE];                  // 6 MB  : att-weighted e
__device__ float g_cur[NN*DD];                    // layer-1 input

// ---------------- K0: copy x into out[:, 0:768] ----------------
__global__ void k_copy_x(const float* __restrict__ x, float* __restrict__ out) {
    int idx = blockIdx.x*blockDim.x + threadIdx.x;
    if (idx >= NN*DD) return;
    int n = idx / DD, c = idx - n*DD;
    out[(size_t)n*(3*DD) + c] = x[idx];
}

// ---------------- K1: wk_a2[l,h,d] = sum_f Wk[l,h,D+d,f] * a[l,h,F+f] ----------------
__global__ void k_wk_a2(const float* __restrict__ Wk, const float* __restrict__ a) {
    int gw   = (blockIdx.x*blockDim.x + threadIdx.x) >> 5;
    int lane = threadIdx.x & 31;
    if (gw >= LL*HH*EE) return;
    int lh = gw / EE;
    int d  = gw - lh*EE;
    const float* wrow = Wk + ((size_t)lh*(DD+EE) + DD + d)*FF;
    const float* arow = a + (size_t)lh*2*FF + FF;
    float s = 0.f;
    #pragma unroll
    for (int p = 0; p < 3; p++) s += wrow[lane + p*32] * arow[lane + p*32];
    #pragma unroll
    for (int o = 16; o; o >>= 1) s += __shfl_xor_sync(0xffffffffu, s, o);
    if (lane == 0) g_wk_a2[gw] = s;
}

// ---------------- K2: s_e = e_flat(65536x768) @ wk_a2^T(768x16), one pass over e ----------------
// 512 blocks x 128 rows.  128 threads: 2 col-groups x 64 row-groups, 2 rows each.
__global__ __launch_bounds__(128) void k_se(const float* __restrict__ e) {
    __shared__ float As[32][132];   // [k][row], padded
    __shared__ float Bs[16][32];    // [col][k]
    int t  = threadIdx.x;
    int cg = t >> 6;                // 0..1 -> 8 cols each
    int rg = t & 63;                // 64 row-groups x 2 rows
    int r0 = blockIdx.x * 128;
    float acc[2][8];
    #pragma unroll
    for (int i = 0; i < 2; i++)
        #pragma unroll
        for (int j = 0; j < 8; j++) acc[i][j] = 0.f;

    for (int kt = 0; kt < 24; kt++) {
        int k0 = kt*32;
        #pragma unroll
        for (int p = 0; p < 8; p++) {             // A tile: 128 rows x 32 k
            int idx = t + p*128;
            int r = idx >> 3, k4 = idx & 7;
            float4 v = *(const float4*)(e + (size_t)(r0 + r)*EE + k0 + k4*4);
            As[k4*4+0][r] = v.x; As[k4*4+1][r] = v.y;
            As[k4*4+2][r] = v.z; As[k4*4+3][r] = v.w;
        }
        #pragma unroll
        for (int p = 0; p < 4; p++) {             // B tile: 16 cols x 32 k
            int idx = t + p*128;
            int c = idx >> 5, k = idx & 31;
            Bs[c][k] = g_wk_a2[c*EE + k0 + k];
        }
        __syncthreads();
        #pragma unroll
        for (int k = 0; k < 32; k++) {
            float bv[8];
            #pragma unroll
            for (int cc = 0; cc < 8; cc++) bv[cc] = Bs[cg*8+cc][k];
            #pragma unroll
            for (int rr = 0; rr < 2; rr++) {
                float av = As[k][rg + rr*64];
                #pragma unroll
                for (int cc = 0; cc < 8; cc++) acc[rr][cc] += av*bv[cc];
            }
        }
        __syncthreads();
    }
    #pragma unroll
    for (int rr = 0; rr < 2; rr++) {
        int row = r0 + rg + rr*64;
        #pragma unroll
        for (int cc = 0; cc < 8; cc++) {
            int c = cg*8 + cc;                    // c = l*8+h
            g_se[(size_t)c*65536 + row] = acc[rr][cc];
        }
    }
}

// ---------------- K3: projections  C(256 x 2304) = cur(256x768) @ [Wq|Wk_x|Wv_x] ----------------
__global__ __launch_bounds__(256) void k_proj(const float* __restrict__ x,
                                              const float* __restrict__ Wq,
                                              const float* __restrict__ Wk,
                                              const float* __restrict__ Wv, int l) {
    const float* cur = (l == 0) ? x : g_cur;
    __shared__ float As[16][68];
    __shared__ float Bs[16][68];
    __shared__ const float* cp[64];
    int t  = threadIdx.x;
    int C0 = blockIdx.x * 64, R0 = blockIdx.y * 64;
    if (t < 64) {
        int gc = C0 + t;
        int sel = gc / 768;
        int rem = gc - sel*768;
        int h = rem / 96, f = rem - h*96;
        const float* base;
        if (sel == 0)      base = Wq + ((size_t)(l*8+h)*768)*96 + f;
        else if (sel == 1) base = Wk + ((size_t)(l*8+h)*1536)*96 + f;
        else               base = Wv + ((size_t)(l*8+h)*1536)*96 + f;
        cp[t] = base;
    }
    float acc[4][4];
    #pragma unroll
    for (int i = 0; i < 4; i++)
        #pragma unroll
        for (int j = 0; j < 4; j++) acc[i][j] = 0.f;
    int tx = t & 15, ty = t >> 4;
    __syncthreads();

    for (int kt = 0; kt < 48; kt++) {
        int k0 = kt*16;
        {   // A: 64 rows x 16 k
            int r = t >> 2, kk = (t & 3)*4;
            float4 v = *(const float4*)(cur + (size_t)(R0+r)*DD + k0 + kk);
            As[kk+0][r] = v.x; As[kk+1][r] = v.y; As[kk+2][r] = v.z; As[kk+3][r] = v.w;
        }
        {   // B: 16 k x 64 cols (d-stride is 96 floats inside W)
            int c = t & 63, kb = (t >> 6)*4;
            const float* bp = cp[c];
            #pragma unroll
            for (int j = 0; j < 4; j++) Bs[kb+j][c] = bp[(size_t)(k0+kb+j)*96];
        }
        __syncthreads();
        #pragma unroll
        for (int k = 0; k < 16; k++) {
            float4 a4 = *(const float4*)&As[k][ty*4];
            float4 b4 = *(const float4*)&Bs[k][tx*4];
            float av[4] = {a4.x, a4.y, a4.z, a4.w};
            float bv[4] = {b4.x, b4.y, b4.z, b4.w};
            #pragma unroll
            for (int rr = 0; rr < 4; rr++)
                #pragma unroll
                for (int cc = 0; cc < 4; cc++) acc[rr][cc] += av[rr]*bv[cc];
        }
        __syncthreads();
    }
    #pragma unroll
    for (int rr = 0; rr < 4; rr++) {
        int n = R0 + ty*4 + rr;
        #pragma unroll
        for (int cc = 0; cc < 4; cc++) {
            int gc = C0 + tx*4 + cc;
            int sel = gc / 768;
            int rem = gc - sel*768;
            int h = rem / 96, f = rem - h*96;
            float* dst = (sel == 0) ? g_hq : (sel == 1 ? g_hk : g_hv);
            dst[((size_t)h*NN + n)*FF + f] = acc[rr][cc];
        }
    }
}

// ---------------- K4: sq = hq . a1 ; sk = hk . a2 ----------------
__global__ void k_sqsk(const float* __restrict__ a, int l) {
    int gw   = (blockIdx.x*blockDim.x + threadIdx.x) >> 5;
    int lane = threadIdx.x & 31;
    if (gw >= 2*HH*NN) return;
    int which = gw >> 11;            // H*N = 2048
    int r = gw & 2047;
    int h = r >> 8, n = r & 255;
    const float* src = which ? g_hk : g_hq;
    const float* row = src + ((size_t)h*NN + n)*FF;
    const float* ar  = a + (size_t)(l*8+h)*192 + which*96;
    float s = 0.f;
    #pragma unroll
    for (int p = 0; p < 3; p++) s += row[lane + p*32]*ar[lane + p*32];
    #pragma unroll
    for (int o = 16; o; o >>= 1) s += __shfl_xor_sync(0xffffffffu, s, o);
    if (lane == 0) (which ? g_sk : g_sq)[h*NN + n] = s;
}

// ---------------- K5: scores + leaky_relu + mask + softmax -> att ----------------
__global__ __launch_bounds__(256) void k_softmax(const int* __restrict__ adj, int l) {
    int i = blockIdx.x, h = blockIdx.y, j = threadIdx.x;
    int lh = l*8 + h;
    float sv = g_sq[h*NN + i] + g_sk[h*NN + j] + g_se[((size_t)lh*NN + i)*NN + j];
    sv = sv > 0.f ? sv : ALPHAV*sv;
    if (adj[i*NN + j] <= 0) sv = NEGV;

    __shared__ float red[8];
    int lane = j & 31, wid = j >> 5;
    float m = sv;
    #pragma unroll
    for (int o = 16; o; o >>= 1) m = fmaxf(m, __shfl_xor_sync(0xffffffffu, m, o));
    if (lane == 0) red[wid] = m;
    __syncthreads();
    float mx = red[0];
    #pragma unroll
    for (int p = 1; p < 8; p++) mx = fmaxf(mx, red[p]);
    __syncthreads();

    float ex = __expf(sv - mx);
    float s = ex;
    #pragma unroll
    for (int o = 16; o; o >>= 1) s += __shfl_xor_sync(0xffffffffu, s, o);
    if (lane == 0) red[wid] = s;
    __syncthreads();
    float tot = red[0];
    #pragma unroll
    for (int p = 1; p < 8; p++) tot += red[p];
    g_att[((size_t)h*NN + i)*NN + j] = ex * (1.0f / tot);
}

// ---------------- K6: ec[h,i,d] = sum_j att[h,i,j] * e[i,j,d]  (one pass over e) ----------------
// grid: (i, dhalf).  Each block: 96 threads x 4 floats = 384 cols (half of 768).
__global__ __launch_bounds__(96) void k_ec(const float* __restrict__ e) {
    int i = blockIdx.x;
    int t = threadIdx.x;
    __shared__ float satt[HH*NN];   // 8KB
    for (int idx = t; idx < HH*NN; idx += 96)
        satt[idx] = g_att[(size_t)(idx >> 8)*NN*NN + (size_t)i*NN + (idx & 255)];
    __syncthreads();

    int d0 = blockIdx.y*384 + t*4;
    float4 acc[8];
    #pragma unroll
    for (int h = 0; h < 8; h++) acc[h] = make_float4(0.f, 0.f, 0.f, 0.f);
    const float* ebase = e + (size_t)i*NN*EE + d0;
    #pragma unroll 1
    for (int j = 0; j < NN; j += 4) {
        float4 ev0 = *(const float4*)(ebase + (size_t)(j+0)*EE);
        float4 ev1 = *(const float4*)(ebase + (size_t)(j+1)*EE);
        float4 ev2 = *(const float4*)(ebase + (size_t)(j+2)*EE);
        float4 ev3 = *(const float4*)(ebase + (size_t)(j+3)*EE);
        #pragma unroll
        for (int h = 0; h < 8; h++) {
            float a0 = satt[h*NN + j+0];
            float a1 = satt[h*NN + j+1];
            float a2 = satt[h*NN + j+2];
            float a3 = satt[h*NN + j+3];
            acc[h].x += a0*ev0.x; acc[h].y += a0*ev0.y; acc[h].z += a0*ev0.z; acc[h].w += a0*ev0.w;
            acc[h].x += a1*ev1.x; acc[h].y += a1*ev1.y; acc[h].z += a1*ev1.z; acc[h].w += a1*ev1.w;
            acc[h].x += a2*ev2.x; acc[h].y += a2*ev2.y; acc[h].z += a2*ev2.z; acc[h].w += a2*ev2.w;
            acc[h].x += a3*ev3.x; acc[h].y += a3*ev3.y; acc[h].z += a3*ev3.z; acc[h].w += a3*ev3.w;
        }
    }
    #pragma unroll
    for (int h = 0; h < 8; h++)
        *(float4*)(g_ec + ((size_t)(h*NN + i))*EE + d0) = acc[h];
}

// ---------------- K7: out = att@hv_x + ec@Wv_e, ELU, write out + g_cur ----------------
// Unified K=1024 GEMM per head: A = [att | ec] (256x1024), B = [hv ; Wv_e] (1024x96)
__global__ __launch_bounds__(256) void k_av(const float* __restrict__ Wv,
                                            float* __restrict__ out, int l) {
    __shared__ float Aat[32][33];
    __shared__ float Bv[32][96];
    int t  = threadIdx.x;
    int I0 = blockIdx.x*32, h = blockIdx.y;
    int ty = t >> 5, fx = t & 31;
    float acc[4][3];
    #pragma unroll
    for (int rr = 0; rr < 4; rr++)
        #pragma unroll
        for (int ff = 0; ff < 3; ff++) acc[rr][ff] = 0.f;

    for (int kt = 0; kt < 32; kt++) {
        int k0 = kt*32;
        #pragma unroll
        for (int p = 0; p < 4; p++) {          // A: 32 rows x 32 k
            int ii = t + p*256;
            int r = ii >> 5, k = ii & 31;
            int kk = k0 + k;
            float v;
            if (kk < 256) v = g_att[((size_t)h*NN + (I0+r))*NN + kk];
            else          v = g_ec [((size_t)h*NN + (I0+r))*EE + kk - 256];
            Aat[k][r] = v;
        }
        #pragma unroll
        for (int p = 0; p < 12; p++) {         // B: 32 k x 96 f
            int ii = t + p*256;
            int k = ii / 96, f = ii - k*96;
            int kk = k0 + k;
            float v;
            if (kk < 256) v = g_hv[((size_t)h*NN + kk)*FF + f];
            else          v = Wv[((size_t)(l*8+h)*1536 + 768 + (kk-256))*96 + f];
            Bv[k][f] = v;
        }
        __syncthreads();
        #pragma unroll
        for (int k = 0; k < 32; k++) {
            float av[4], bv[3];
            #pragma unroll
            for (int rr = 0; rr < 4; rr++) av[rr] = Aat[k][ty*4+rr];
            #pragma unroll
            for (int ff = 0; ff < 3; ff++) bv[ff] = Bv[k][fx*3+ff];
            #pragma unroll
            for (int rr = 0; rr < 4; rr++)
                #pragma unroll
                for (int ff = 0; ff < 3; ff++) acc[rr][ff] += av[rr]*bv[ff];
        }
        __syncthreads();
    }
    #pragma unroll
    for (int rr = 0; rr < 4; rr++) {
        int n = I0 + ty*4 + rr;
        #pragma unroll
        for (int ff = 0; ff < 3; ff++) {
            int col = h*96 + fx*3 + ff;
            float o = acc[rr][ff];
            o = o > 0.f ? o : (__expf(o) - 1.f);       // ELU
            out[(size_t)n*2304 + 768*(l+1) + col] = o;
            g_cur[n*768 + col] = o;
        }
    }
}

// ---------------- launch ----------------
extern "C" void kernel_launch(void* const* d_in, const int* in_sizes, int n_in,
                              void* d_out, int out_size) {
    const float* x   = (const float*)d_in[0];
    const int*   adj = (const int*)  d_in[1];
    const float* e   = (const float*)d_in[2];
    const float* Wq  = (const float*)d_in[3];
    const float* Wk  = (const float*)d_in[4];
    const float* Wv  = (const float*)d_in[5];
    const float* a   = (const float*)d_in[6];
    float* out = (float*)d_out;

    k_copy_x<<<(NN*DD + 255)/256, 256>>>(x, out);
    k_wk_a2<<<(LL*HH*EE*32 + 255)/256, 256>>>(Wk, a);
    k_se<<<512, 128>>>(e);

    for (int l = 0; l < LL; l++) {
        k_proj<<<dim3(36, 4), 256>>>(x, Wq, Wk, Wv, l);
        k_sqsk<<<512, 256>>>(a, l);
        k_softmax<<<dim3(NN, HH), 256>>>(adj, l);
        k_ec<<<dim3(NN, 2), 96>>>(e);
        k_av<<<dim3(8, 8), 256>>>(Wv, out, l);
    }
}

// round 4
// speedup vs baseline: 1.2849x; 1.2849x over previous
#include <cuda_runtime.h>
#include <cstdint>

#define NN 256
#define DD 768
#define EE 768
#define FF 96
#define HH 8
#define LL 2
#define ALPHAV 0.2f
#define NEGV (-9000000000000000.0f)

// ---------------- device scratch (no allocations allowed) ----------------
__device__ float g_wk_a2[LL*HH*EE];               // 48 KB : Wk_e @ a2 per (l,h)
__device__ float g_se[(size_t)LL*HH*NN*NN];       // 4 MB  : edge score contribution, both layers
__device__ float g_hq[HH*NN*FF];                  // per-layer projections
__device__ float g_hk[HH*NN*FF];
__device__ float g_hv[HH*NN*FF];
__device__ float g_sq[HH*NN];
__device__ float g_sk[HH*NN];
__device__ float g_att[HH*NN*NN];                 // 2 MB
__device__ float g_ec[HH*NN*EE];                  // 6 MB  : att-weighted e
__device__ float g_cur[NN*DD];                    // layer-1 input

// ---------------- K0: copy x into out[:, 0:768] ----------------
__global__ void k_copy_x(const float* __restrict__ x, float* __restrict__ out) {
    int idx = blockIdx.x*blockDim.x + threadIdx.x;
    if (idx >= NN*DD) return;
    int n = idx / DD, c = idx - n*DD;
    out[(size_t)n*(3*DD) + c] = x[idx];
}

// ---------------- K1: wk_a2[l,h,d] = sum_f Wk[l,h,D+d,f] * a[l,h,F+f] ----------------
__global__ void k_wk_a2(const float* __restrict__ Wk, const float* __restrict__ a) {
    int gw   = (blockIdx.x*blockDim.x + threadIdx.x) >> 5;
    int lane = threadIdx.x & 31;
    if (gw >= LL*HH*EE) return;
    int lh = gw / EE;
    int d  = gw - lh*EE;
    const float* wrow = Wk + ((size_t)lh*(DD+EE) + DD + d)*FF;
    const float* arow = a + (size_t)lh*2*FF + FF;
    float s = 0.f;
    #pragma unroll
    for (int p = 0; p < 3; p++) s += wrow[lane + p*32] * arow[lane + p*32];
    #pragma unroll
    for (int o = 16; o; o >>= 1) s += __shfl_xor_sync(0xffffffffu, s, o);
    if (lane == 0) g_wk_a2[gw] = s;
}

// ---------------- K2: s_e = e_flat(65536x768) @ wk_a2^T(768x16), one pass over e ----------------
// 512 blocks x 128 rows.  128 threads: 2 col-groups x 64 row-groups, 2 rows each.
__global__ __launch_bounds__(128) void k_se(const float* __restrict__ e) {
    __shared__ float As[32][132];   // [k][row], padded
    __shared__ float Bs[16][32];    // [col][k]
    int t  = threadIdx.x;
    int cg = t >> 6;                // 0..1 -> 8 cols each
    int rg = t & 63;                // 64 row-groups x 2 rows
    int r0 = blockIdx.x * 128;
    float acc[2][8];
    #pragma unroll
    for (int i = 0; i < 2; i++)
        #pragma unroll
        for (int j = 0; j < 8; j++) acc[i][j] = 0.f;

    for (int kt = 0; kt < 24; kt++) {
        int k0 = kt*32;
        #pragma unroll
        for (int p = 0; p < 8; p++) {             // A tile: 128 rows x 32 k
            int idx = t + p*128;
            int r = idx >> 3, k4 = idx & 7;
            float4 v = *(const float4*)(e + (size_t)(r0 + r)*EE + k0 + k4*4);
            As[k4*4+0][r] = v.x; As[k4*4+1][r] = v.y;
            As[k4*4+2][r] = v.z; As[k4*4+3][r] = v.w;
        }
        #pragma unroll
        for (int p = 0; p < 4; p++) {             // B tile: 16 cols x 32 k
            int idx = t + p*128;
            int c = idx >> 5, k = idx & 31;
            Bs[c][k] = g_wk_a2[c*EE + k0 + k];
        }
        __syncthreads();
        #pragma unroll
        for (int k = 0; k < 32; k++) {
            float bv[8];
            #pragma unroll
            for (int cc = 0; cc < 8; cc++) bv[cc] = Bs[cg*8+cc][k];
            #pragma unroll
            for (int rr = 0; rr < 2; rr++) {
                float av = As[k][rg + rr*64];
                #pragma unroll
                for (int cc = 0; cc < 8; cc++) acc[rr][cc] += av*bv[cc];
            }
        }
        __syncthreads();
    }
    #pragma unroll
    for (int rr = 0; rr < 2; rr++) {
        int row = r0 + rg + rr*64;
        #pragma unroll
        for (int cc = 0; cc < 8; cc++) {
            int c = cg*8 + cc;                    // c = l*8+h
            g_se[(size_t)c*65536 + row] = acc[rr][cc];
        }
    }
}

// ---------------- K3: projections  C(256 x 2304) = cur(256x768) @ [Wq|Wk_x|Wv_x] ----------------
// Tile 32 rows x 64 cols, grid (36, 8) = 288 blocks, k-tile 32 with register prefetch.
__global__ __launch_bounds__(256) void k_proj(const float* __restrict__ x,
                                              const float* __restrict__ Wq,
                                              const float* __restrict__ Wk,
                                              const float* __restrict__ Wv, int l) {
    const float* cur = (l == 0) ? x : g_cur;
    __shared__ float As[32][36];
    __shared__ float Bs[32][68];
    __shared__ const float* cp[64];
    int t  = threadIdx.x;
    int C0 = blockIdx.x * 64, R0 = blockIdx.y * 32;
    if (t < 64) {
        int gc = C0 + t;
        int sel = gc / 768;
        int rem = gc - sel*768;
        int h = rem / 96, f = rem - h*96;
        const float* base;
        if (sel == 0)      base = Wq + ((size_t)(l*8+h)*768)*96 + f;
        else if (sel == 1) base = Wk + ((size_t)(l*8+h)*1536)*96 + f;
        else               base = Wv + ((size_t)(l*8+h)*1536)*96 + f;
        cp[t] = base;
    }
    __syncthreads();

    int tx = t & 15, ty = t >> 4;             // 16 col-groups x 16 row-groups
    int ar = t >> 3, ak = (t & 7)*4;          // A load: row, k4
    int bc = t & 63, bk = (t >> 6)*8;         // B load: col, k-base
    const float* bp = cp[bc];
    const float* ap = cur + (size_t)(R0 + ar)*DD + ak;

    float acc[2][4];
    #pragma unroll
    for (int i = 0; i < 2; i++)
        #pragma unroll
        for (int j = 0; j < 4; j++) acc[i][j] = 0.f;

    float4 pa = *(const float4*)(ap);
    float  pb[8];
    #pragma unroll
    for (int j = 0; j < 8; j++) pb[j] = bp[(size_t)(bk+j)*96];

    for (int kt = 0; kt < 24; kt++) {
        // stage current prefetch into smem
        As[ak+0][ar] = pa.x; As[ak+1][ar] = pa.y; As[ak+2][ar] = pa.z; As[ak+3][ar] = pa.w;
        #pragma unroll
        for (int j = 0; j < 8; j++) Bs[bk+j][bc] = pb[j];
        __syncthreads();
        // prefetch next tile while computing
        if (kt < 23) {
            int k0 = (kt+1)*32;
            pa = *(const float4*)(ap + k0);
            #pragma unroll
            for (int j = 0; j < 8; j++) pb[j] = bp[(size_t)(k0+bk+j)*96];
        }
        #pragma unroll
        for (int k = 0; k < 32; k++) {
            float2 a2 = *(const float2*)&As[k][ty*2];
            float4 b4 = *(const float4*)&Bs[k][tx*4];
            float av[2] = {a2.x, a2.y};
            float bv[4] = {b4.x, b4.y, b4.z, b4.w};
            #pragma unroll
            for (int rr = 0; rr < 2; rr++)
                #pragma unroll
                for (int cc = 0; cc < 4; cc++) acc[rr][cc] += av[rr]*bv[cc];
        }
        __syncthreads();
    }
    #pragma unroll
    for (int rr = 0; rr < 2; rr++) {
        int n = R0 + ty*2 + rr;
        #pragma unroll
        for (int cc = 0; cc < 4; cc++) {
            int gc = C0 + tx*4 + cc;
            int sel = gc / 768;
            int rem = gc - sel*768;
            int h = rem / 96, f = rem - h*96;
            float* dst = (sel == 0) ? g_hq : (sel == 1 ? g_hk : g_hv);
            dst[((size_t)h*NN + n)*FF + f] = acc[rr][cc];
        }
    }
}

// ---------------- K4: sq = hq . a1 ; sk = hk . a2 ----------------
__global__ void k_sqsk(const float* __restrict__ a, int l) {
    int gw   = (blockIdx.x*blockDim.x + threadIdx.x) >> 5;
    int lane = threadIdx.x & 31;
    if (gw >= 2*HH*NN) return;
    int which = gw >> 11;            // H*N = 2048
    int r = gw & 2047;
    int h = r >> 8, n = r & 255;
    const float* src = which ? g_hk : g_hq;
    const float* row = src + ((size_t)h*NN + n)*FF;
    const float* ar  = a + (size_t)(l*8+h)*192 + which*96;
    float s = 0.f;
    #pragma unroll
    for (int p = 0; p < 3; p++) s += row[lane + p*32]*ar[lane + p*32];
    #pragma unroll
    for (int o = 16; o; o >>= 1) s += __shfl_xor_sync(0xffffffffu, s, o);
    if (lane == 0) (which ? g_sk : g_sq)[h*NN + n] = s;
}

// ---------------- K5: scores + leaky_relu + mask + softmax -> att ----------------
__global__ __launch_bounds__(256) void k_softmax(const int* __restrict__ adj, int l) {
    int i = blockIdx.x, h = blockIdx.y, j = threadIdx.x;
    int lh = l*8 + h;
    float sv = g_sq[h*NN + i] + g_sk[h*NN + j] + g_se[((size_t)lh*NN + i)*NN + j];
    sv = sv > 0.f ? sv : ALPHAV*sv;
    if (adj[i*NN + j] <= 0) sv = NEGV;

    __shared__ float red[8];
    int lane = j & 31, wid = j >> 5;
    float m = sv;
    #pragma unroll
    for (int o = 16; o; o >>= 1) m = fmaxf(m, __shfl_xor_sync(0xffffffffu, m, o));
    if (lane == 0) red[wid] = m;
    __syncthreads();
    float mx = red[0];
    #pragma unroll
    for (int p = 1; p < 8; p++) mx = fmaxf(mx, red[p]);
    __syncthreads();

    float ex = __expf(sv - mx);
    float s = ex;
    #pragma unroll
    for (int o = 16; o; o >>= 1) s += __shfl_xor_sync(0xffffffffu, s, o);
    if (lane == 0) red[wid] = s;
    __syncthreads();
    float tot = red[0];
    #pragma unroll
    for (int p = 1; p < 8; p++) tot += red[p];
    g_att[((size_t)h*NN + i)*NN + j] = ex * (1.0f / tot);
}

// ---------------- K6: ec[h,i,d] = sum_j att[h,i,j] * e[i,j,d]  (one pass over e) ----------------
// grid: (i, dhalf).  Each block: 96 threads x 4 floats = 384 cols.  j-unroll 8 for MLP.
__global__ __launch_bounds__(96) void k_ec(const float* __restrict__ e) {
    int i = blockIdx.x;
    int t = threadIdx.x;
    __shared__ float satt[HH*NN];   // 8KB
    for (int idx = t; idx < HH*NN; idx += 96)
        satt[idx] = g_att[(size_t)(idx >> 8)*NN*NN + (size_t)i*NN + (idx & 255)];
    __syncthreads();

    int d0 = blockIdx.y*384 + t*4;
    float4 acc[8];
    #pragma unroll
    for (int h = 0; h < 8; h++) acc[h] = make_float4(0.f, 0.f, 0.f, 0.f);
    const float* ebase = e + (size_t)i*NN*EE + d0;
    #pragma unroll 1
    for (int j = 0; j < NN; j += 8) {
        float4 ev[8];
        #pragma unroll
        for (int u = 0; u < 8; u++)
            ev[u] = *(const float4*)(ebase + (size_t)(j+u)*EE);
        #pragma unroll
        for (int h = 0; h < 8; h++) {
            #pragma unroll
            for (int u = 0; u < 8; u++) {
                float av = satt[h*NN + j + u];
                acc[h].x += av*ev[u].x; acc[h].y += av*ev[u].y;
                acc[h].z += av*ev[u].z; acc[h].w += av*ev[u].w;
            }
        }
    }
    #pragma unroll
    for (int h = 0; h < 8; h++)
        *(float4*)(g_ec + ((size_t)(h*NN + i))*EE + d0) = acc[h];
}

// ---------------- K7: out = att@hv_x + ec@Wv_e, ELU, write out + g_cur ----------------
// Unified K=1024 GEMM per head: A = [att | ec] (256x1024), B = [hv ; Wv_e] (1024x96)
// Tile 16 rows x 96 cols, grid (16, 8) = 128 blocks.
__global__ __launch_bounds__(256) void k_av(const float* __restrict__ Wv,
                                            float* __restrict__ out, int l) {
    __shared__ float Aat[32][17];
    __shared__ float Bv[32][96];
    int t  = threadIdx.x;
    int I0 = blockIdx.x*16, h = blockIdx.y;
    int ty = t >> 5, fx = t & 31;             // 8 row-groups x 2 rows, 32 col-groups x 3
    float acc[2][3];
    #pragma unroll
    for (int rr = 0; rr < 2; rr++)
        #pragma unroll
        for (int ff = 0; ff < 3; ff++) acc[rr][ff] = 0.f;

    for (int kt = 0; kt < 32; kt++) {
        int k0 = kt*32;
        #pragma unroll
        for (int p = 0; p < 2; p++) {          // A: 16 rows x 32 k
            int ii = t + p*256;
            int r = ii >> 5, k = ii & 31;
            int kk = k0 + k;
            float v;
            if (kk < 256) v = g_att[((size_t)h*NN + (I0+r))*NN + kk];
            else          v = g_ec [((size_t)h*NN + (I0+r))*EE + kk - 256];
            Aat[k][r] = v;
        }
        #pragma unroll
        for (int p = 0; p < 12; p++) {         // B: 32 k x 96 f
            int ii = t + p*256;
            int k = ii / 96, f = ii - k*96;
            int kk = k0 + k;
            float v;
            if (kk < 256) v = g_hv[((size_t)h*NN + kk)*FF + f];
            else          v = Wv[((size_t)(l*8+h)*1536 + 768 + (kk-256))*96 + f];
            Bv[k][f] = v;
        }
        __syncthreads();
        #pragma unroll
        for (int k = 0; k < 32; k++) {
            float av[2], bv[3];
            #pragma unroll
            for (int rr = 0; rr < 2; rr++) av[rr] = Aat[k][ty*2+rr];
            #pragma unroll
            for (int ff = 0; ff < 3; ff++) bv[ff] = Bv[k][fx*3+ff];
            #pragma unroll
            for (int rr = 0; rr < 2; rr++)
                #pragma unroll
                for (int ff = 0; ff < 3; ff++) acc[rr][ff] += av[rr]*bv[ff];
        }
        __syncthreads();
    }
    #pragma unroll
    for (int rr = 0; rr < 2; rr++) {
        int n = I0 + ty*2 + rr;
        #pragma unroll
        for (int ff = 0; ff < 3; ff++) {
            int col = h*96 + fx*3 + ff;
            float o = acc[rr][ff];
            o = o > 0.f ? o : (__expf(o) - 1.f);       // ELU
            out[(size_t)n*2304 + 768*(l+1) + col] = o;
            g_cur[n*768 + col] = o;
        }
    }
}

// ---------------- launch ----------------
extern "C" void kernel_launch(void* const* d_in, const int* in_sizes, int n_in,
                              void* d_out, int out_size) {
    const float* x   = (const float*)d_in[0];
    const int*   adj = (const int*)  d_in[1];
    const float* e   = (const float*)d_in[2];
    const float* Wq  = (const float*)d_in[3];
    const float* Wk  = (const float*)d_in[4];
    const float* Wv  = (const float*)d_in[5];
    const float* a   = (const float*)d_in[6];
    float* out = (float*)d_out;

    k_copy_x<<<(NN*DD + 255)/256, 256>>>(x, out);
    k_wk_a2<<<(LL*HH*EE*32 + 255)/256, 256>>>(Wk, a);
    k_se<<<512, 128>>>(e);

    for (int l = 0; l < LL; l++) {
        k_proj<<<dim3(36, 8), 256>>>(x, Wq, Wk, Wv, l);
        k_sqsk<<<512, 256>>>(a, l);
        k_softmax<<<dim3(NN, HH), 256>>>(adj, l);
        k_ec<<<dim3(NN, 2), 96>>>(e);
        k_av<<<dim3(16, 8), 256>>>(Wv, out, l);
    }
}